// round 6
// baseline (speedup 1.0000x reference)
#include <cuda_runtime.h>

#define TLEN 65536
#define INPD 5
#define HD 100
#define HP 104            // padded h stride (keeps both buffers 16B aligned)
#define G4 400            // 4*HD
#define CHUNK 8
#define NCHUNK (TLEN / CHUNK)
#define XG_TILE 16

// ---------------- static device scratch ----------------
__device__ float g_xg0[(size_t)TLEN * G4];
__device__ float g_xg1[(size_t)TLEN * G4];
__device__ float g_h1[(size_t)TLEN * HD];
__device__ float g_h2[(size_t)TLEN * HD];
__device__ int   g_prog0;           // layer-0 chunks completed
__device__ int   g_ready[NCHUNK];   // xg1 chunk ready flags

// ---------------- helpers ----------------
__device__ __forceinline__ float tanh_ap(float x) {
    float y;
    asm("tanh.approx.f32 %0, %1;" : "=f"(y) : "f"(x));
    return y;
}
__device__ __forceinline__ float sigmoid_ap(float x) {
    return __fmaf_rn(0.5f, tanh_ap(0.5f * x), 0.5f);
}
__device__ __forceinline__ int ld_acq(const int* p) {
    int v;
    asm volatile("ld.acquire.gpu.global.b32 %0, [%1];" : "=r"(v) : "l"(p) : "memory");
    return v;
}
// predicated stores (no BSSY/BSYNC divergence)
__device__ __forceinline__ void sts_pred(int pred, unsigned addr, float v) {
    asm volatile("{ .reg .pred p; setp.ne.s32 p, %0, 0; @p st.shared.f32 [%1], %2; }"
                 :: "r"(pred), "r"(addr), "f"(v));
}
__device__ __forceinline__ void stg_pred(int pred, float* addr, float v) {
    asm volatile("{ .reg .pred p; setp.ne.s32 p, %0, 0; @p st.global.cs.f32 [%1], %2; }"
                 :: "r"(pred), "l"(addr), "f"(v));
}

// plain fp32 100-dot: 25 float4 chunks, 8 independent FFMA chains
__device__ __forceinline__ float dot100f(const float4* __restrict__ w4,
                                         const float* __restrict__ hvec, float init) {
    const float4* hp = (const float4*)hvec;
    float a0 = init, a1 = 0.f, a2 = 0.f, a3 = 0.f;
    float a4 = 0.f, a5 = 0.f, a6 = 0.f, a7 = 0.f;
#pragma unroll
    for (int k = 0; k < 25; k++) {
        float4 hv = hp[k];
        float4 wv = w4[k];
        if (k & 1) {
            a4 = __fmaf_rn(wv.x, hv.x, a4);
            a5 = __fmaf_rn(wv.y, hv.y, a5);
            a6 = __fmaf_rn(wv.z, hv.z, a6);
            a7 = __fmaf_rn(wv.w, hv.w, a7);
        } else {
            a0 = __fmaf_rn(wv.x, hv.x, a0);
            a1 = __fmaf_rn(wv.y, hv.y, a1);
            a2 = __fmaf_rn(wv.z, hv.z, a2);
            a3 = __fmaf_rn(wv.w, hv.w, a3);
        }
    }
    return ((a0 + a4) + (a1 + a5)) + ((a2 + a6) + (a3 + a7));
}

__device__ __forceinline__ void load_wrow4(float4* w4, const float* row) {
    const float4* wr = (const float4*)row;
#pragma unroll
    for (int k = 0; k < 25; k++) w4[k] = __ldg(wr + k);
}

// ---------------- phase 1: xg0 = Wih0 @ x[t] + bih0 + bhh0 (+ flag reset) ------
__global__ void xg0_kernel(const float* __restrict__ x,
                           const float* __restrict__ Wih0,
                           const float* __restrict__ bih0,
                           const float* __restrict__ bhh0) {
    int g = threadIdx.x;                 // 0..399
    if (blockIdx.x == 0) {               // reset cross-block flags for this run
        for (int i = g; i < NCHUNK; i += G4) g_ready[i] = 0;
        if (g == 0) g_prog0 = 0;
    }
    int t0 = blockIdx.x * XG_TILE;
    float w0 = __ldg(Wih0 + g * INPD + 0);
    float w1 = __ldg(Wih0 + g * INPD + 1);
    float w2 = __ldg(Wih0 + g * INPD + 2);
    float w3 = __ldg(Wih0 + g * INPD + 3);
    float w4 = __ldg(Wih0 + g * INPD + 4);
    float b = __ldg(bih0 + g) + __ldg(bhh0 + g);
#pragma unroll
    for (int tt = 0; tt < XG_TILE; tt++) {
        const float* xr = x + (size_t)(t0 + tt) * INPD;
        float acc = b;
        acc = __fmaf_rn(w0, __ldg(xr + 0), acc);
        acc = __fmaf_rn(w1, __ldg(xr + 1), acc);
        acc = __fmaf_rn(w2, __ldg(xr + 2), acc);
        acc = __fmaf_rn(w3, __ldg(xr + 3), acc);
        acc = __fmaf_rn(w4, __ldg(xr + 4), acc);
        g_xg0[(size_t)(t0 + tt) * G4 + g] = acc;
    }
}

// ---------------- recurrence body (one block, 400 threads) ----------------
// tid = 4*j + q : unit j (0..99), gate q (0:i 1:f 2:g 3:o); row = q*HD + j
template <bool RELEASE, bool WAIT>
__device__ void rec_body(const float* __restrict__ Whh,
                         const float* __restrict__ xg,
                         float* __restrict__ hout,
                         float* __restrict__ h_s /* [2][HP] smem */) {
    int tid = threadIdx.x;
    int j = tid >> 2, q = tid & 3;
    int row = q * HD + j;
    unsigned mask = __activemask();
    int lsrc = (tid & 31) & ~3;          // lane of gate i in this unit's group
    int isq0 = (q == 0);

    // unified activation: act = sc * tanh(sc * gv) + off
    float sc  = (q == 2) ? 1.0f : 0.5f;
    float off = (q == 2) ? 0.0f : 0.5f;

    float4 w4[25];
    load_wrow4(w4, Whh + (size_t)row * HD);

    // smem store addresses for h (two alternating buffers), 32-bit shared addrs
    unsigned hsA = (unsigned)__cvta_generic_to_shared(h_s + HP + j);  // written when s even
    unsigned hsB = (unsigned)__cvta_generic_to_shared(h_s + j);       // written when s odd

    if (tid < 2 * HP) h_s[tid] = 0.f;
    float c = 0.f;

    if (WAIT) {
        while (ld_acq(&g_ready[0]) == 0) __nanosleep(40);
    }
    float xr[CHUNK];
    {
        const float* xp = xg + row;
#pragma unroll
        for (int s = 0; s < CHUNK; s++) xr[s] = __ldcg(xp + (size_t)s * G4);
    }
    __syncthreads();

#pragma unroll 1
    for (int c0 = 0; c0 < NCHUNK; c0++) {
        float xc[CHUNK];
#pragma unroll
        for (int s = 0; s < CHUNK; s++) xc[s] = xr[s];

        if (c0 + 1 < NCHUNK) {           // prefetch next chunk, off critical path
            if (WAIT) {
                while (ld_acq(&g_ready[c0 + 1]) == 0) __nanosleep(40);
            }
            const float* xp = xg + (size_t)(c0 + 1) * CHUNK * G4 + row;
#pragma unroll
            for (int s = 0; s < CHUNK; s++) xr[s] = __ldcg(xp + (size_t)s * G4);
        }

#pragma unroll
        for (int s = 0; s < CHUNK; s++) {              // fully unrolled
            float gv = dot100f(w4, h_s + (s & 1) * HP, xc[s]);
            float act = __fmaf_rn(sc, tanh_ap(sc * gv), off);
            // distribute the 4 gates of this unit to all 4 lanes (branch-free)
            float iv = __shfl_sync(mask, act, lsrc + 0, 32);
            float fv = __shfl_sync(mask, act, lsrc + 1, 32);
            float gg = __shfl_sync(mask, act, lsrc + 2, 32);
            float ov = __shfl_sync(mask, act, lsrc + 3, 32);
            c = __fmaf_rn(fv, c, iv * gg);             // identical on all 4 lanes
            float h = ov * tanh_ap(c);
            sts_pred(isq0, (s & 1) ? hsB : hsA, h);
            stg_pred(isq0, hout + (size_t)(c0 * CHUNK + s) * HD + j, h);
            __syncthreads();
        }

        if (RELEASE && tid == 0) {
            __threadfence();
            *((volatile int*)&g_prog0) = c0 + 1;
        }
    }
}

// ---------------- xg1 streaming body (2 blocks, alternate chunks) -------------
__device__ void xg_body(const float* __restrict__ Wih1,
                        const float* __restrict__ bih1,
                        const float* __restrict__ bhh1, int b,
                        float* __restrict__ hbuf /* [CHUNK][HP] smem */) {
    int tid = threadIdx.x;               // 0..399 = gate row

    float4 w4[25];
    load_wrow4(w4, Wih1 + (size_t)tid * HD);
    float bb = __ldg(bih1 + tid) + __ldg(bhh1 + tid);

#pragma unroll 1
    for (int c0 = b; c0 < NCHUNK; c0 += 2) {
        while (ld_acq(&g_prog0) < c0 + 1) __nanosleep(40);
        __syncthreads();                 // protect hbuf reuse
        for (int i = tid; i < CHUNK * HD; i += G4)
            hbuf[(i / HD) * HP + (i % HD)] = __ldcg(g_h1 + (size_t)c0 * CHUNK * HD + i);
        __syncthreads();

#pragma unroll
        for (int s = 0; s < CHUNK; s++) {
            float v = dot100f(w4, hbuf + s * HP, bb);
            __stcg(g_xg1 + (size_t)(c0 * CHUNK + s) * G4 + tid, v);
        }
        __syncthreads();
        if (tid == 0) {
            __threadfence();
            *((volatile int*)&g_ready[c0]) = 1;
        }
    }
}

// ---------------- fused pipelined kernel: grid = 4 blocks ----------------
__global__ __launch_bounds__(G4, 1)
void fused_kernel(const float* __restrict__ Whh0,
                  const float* __restrict__ Whh1,
                  const float* __restrict__ Wih1,
                  const float* __restrict__ bih1,
                  const float* __restrict__ bhh1) {
    __shared__ __align__(16) float smem_pool[CHUNK * HP];   // 3328 B
    int b = blockIdx.x;
    if (b == 0)
        rec_body<true, false>(Whh0, g_xg0, g_h1, smem_pool);
    else if (b <= 2)
        xg_body(Wih1, bih1, bhh1, b - 1, smem_pool);
    else
        rec_body<false, true>(Whh1, g_xg1, g_h2, smem_pool);
}

// ---------------- final linear + sigmoid ----------------
__global__ void out_kernel(const float* __restrict__ Wlin,
                           const float* __restrict__ blin,
                           float* __restrict__ out) {
    int warp = (blockIdx.x * blockDim.x + threadIdx.x) >> 5;
    int lane = threadIdx.x & 31;
    if (warp >= TLEN) return;
    const float* hr = g_h2 + (size_t)warp * HD;
    float acc = 0.f;
#pragma unroll
    for (int k = 0; k < 4; k++) {
        int idx = lane + 32 * k;
        if (idx < HD) acc = __fmaf_rn(hr[idx], __ldg(Wlin + idx), acc);
    }
#pragma unroll
    for (int o = 16; o; o >>= 1) acc += __shfl_down_sync(0xffffffffu, acc, o);
    if (lane == 0) out[warp] = sigmoid_ap(acc + __ldg(blin));
}

// ---------------- launch ----------------
extern "C" void kernel_launch(void* const* d_in, const int* in_sizes, int n_in,
                              void* d_out, int out_size) {
    const float* x    = (const float*)d_in[0];
    const float* Wih0 = (const float*)d_in[1];
    const float* Whh0 = (const float*)d_in[2];
    const float* bih0 = (const float*)d_in[3];
    const float* bhh0 = (const float*)d_in[4];
    const float* Wih1 = (const float*)d_in[5];
    const float* Whh1 = (const float*)d_in[6];
    const float* bih1 = (const float*)d_in[7];
    const float* bhh1 = (const float*)d_in[8];
    const float* Wlin = (const float*)d_in[9];
    const float* blin = (const float*)d_in[10];
    float* out = (float*)d_out;

    xg0_kernel<<<TLEN / XG_TILE, G4>>>(x, Wih0, bih0, bhh0);
    fused_kernel<<<4, G4>>>(Whh0, Whh1, Wih1, bih1, bhh1);
    out_kernel<<<(TLEN * 32) / 256, 256>>>(Wlin, blin, out);
}